// round 6
// baseline (speedup 1.0000x reference)
#include <cuda_runtime.h>
#include <cuda_fp16.h>

#define THREADS 1024
#define RPB     8
#define NCTA    128
#define SEQ     1024
#define GATES   512
#define HID     128

// ---- smem byte offsets ----
#define B_OFF     0         // fused B frags: 8 kt * 512B (lane 16B = bh.x2 | bl.x2)
#define GS_OFF    4096      // gates [8 rows][516 words f32] = 16512
#define XBUF_OFF  20608     // x double buffer 2*8 f32
#define RED_OFF   20672     // output reduction 128*8 f32
#define SMEM_TOTAL 24768

#define GS_STRIDE 516
#define LOG2E     1.4426950408889634f

typedef unsigned int u32;

static __device__ __forceinline__ void mma_f16(float* d, const uint4& a, u32 b0, u32 b1) {
    asm volatile("mma.sync.aligned.m16n8k16.row.col.f32.f16.f16.f32 "
        "{%0,%1,%2,%3}, {%4,%5,%6,%7}, {%8,%9}, {%0,%1,%2,%3};"
        : "+f"(d[0]), "+f"(d[1]), "+f"(d[2]), "+f"(d[3])
        : "r"(a.x), "r"(a.y), "r"(a.z), "r"(a.w), "r"(b0), "r"(b1));
}
static __device__ __forceinline__ float ex2f(float x) {
    float r; asm("ex2.approx.f32 %0, %1;" : "=f"(r) : "f"(x)); return r;
}
static __device__ __forceinline__ float rcpf(float x) {
    float r; asm("rcp.approx.f32 %0, %1;" : "=f"(r) : "f"(x)); return r;
}
static __device__ __forceinline__ u32 pack_h2(float a, float b) {
    __half2 h = __halves2half2(__float2half_rn(a), __float2half_rn(b));
    return *reinterpret_cast<u32*>(&h);
}
static __device__ __forceinline__ float fast_tanh1(float x) {
    x = fminf(fmaxf(x, -15.f), 15.f);
    float e = ex2f(x * (2.f * LOG2E));
    return (e - 1.f) * rcpf(e + 1.f);
}
// 4 activations sharing ONE rcp
static __device__ __forceinline__ void act4(float* v, bool is_tanh) {
    if (is_tanh) {
        float e0 = ex2f(fminf(fmaxf(v[0], -8.f), 8.f) * (2.f * LOG2E));
        float e1 = ex2f(fminf(fmaxf(v[1], -8.f), 8.f) * (2.f * LOG2E));
        float e2 = ex2f(fminf(fmaxf(v[2], -8.f), 8.f) * (2.f * LOG2E));
        float e3 = ex2f(fminf(fmaxf(v[3], -8.f), 8.f) * (2.f * LOG2E));
        float d0 = e0 + 1.f, d1 = e1 + 1.f, d2 = e2 + 1.f, d3 = e3 + 1.f;
        float p01 = d0 * d1, p23 = d2 * d3;
        float r = rcpf(p01 * p23);
        v[0] = (e0 - 1.f) * (r * d1 * p23);
        v[1] = (e1 - 1.f) * (r * d0 * p23);
        v[2] = (e2 - 1.f) * (r * p01 * d3);
        v[3] = (e3 - 1.f) * (r * p01 * d2);
    } else {
        float e0 = ex2f(fminf(fmaxf(v[0], -14.f), 14.f) * (-LOG2E));
        float e1 = ex2f(fminf(fmaxf(v[1], -14.f), 14.f) * (-LOG2E));
        float e2 = ex2f(fminf(fmaxf(v[2], -14.f), 14.f) * (-LOG2E));
        float e3 = ex2f(fminf(fmaxf(v[3], -14.f), 14.f) * (-LOG2E));
        float d0 = e0 + 1.f, d1 = e1 + 1.f, d2 = e2 + 1.f, d3 = e3 + 1.f;
        float p01 = d0 * d1, p23 = d2 * d3;
        float r = rcpf(p01 * p23);
        v[0] = r * d1 * p23;
        v[1] = r * d0 * p23;
        v[2] = r * p01 * d3;
        v[3] = r * p01 * d2;
    }
}

__global__ void __launch_bounds__(THREADS, 1)
lstm_w32_kernel(const float* __restrict__ x,  const float* __restrict__ Wi,
                const float* __restrict__ Wh, const float* __restrict__ b,
                const float* __restrict__ Wd, const float* __restrict__ bd,
                float* __restrict__ out)
{
    extern __shared__ char smem[];
    const int tid  = threadIdx.x;
    const int w    = tid >> 5;           // warp = m-tile 0..31, gate rows [16w, 16w+16)
    const int lane = tid & 31;
    const int g    = lane >> 2;
    const int q    = lane & 3;
    const int r0   = blockIdx.x * RPB;

    // ---- A = Wh^T fp16 fragments -> registers (one m-tile per warp) ----
    uint4 areg[8];                       // [k-tile], 32 regs
    {
        int j0 = 16 * w + g, j1 = j0 + 8;
#pragma unroll
        for (int kt = 0; kt < 8; kt++) {
            int c0 = kt * 16 + 2 * q, c2 = c0 + 8;
            areg[kt].x = pack_h2(Wh[c0 * GATES + j0], Wh[(c0 + 1) * GATES + j0]);
            areg[kt].y = pack_h2(Wh[c0 * GATES + j1], Wh[(c0 + 1) * GATES + j1]);
            areg[kt].z = pack_h2(Wh[c2 * GATES + j0], Wh[(c2 + 1) * GATES + j0]);
            areg[kt].w = pack_h2(Wh[c2 * GATES + j1], Wh[(c2 + 1) * GATES + j1]);
        }
    }

    // zero fused B tiles (h0 = 0)
    for (int i = tid; i < 4096 / 4; i += THREADS)
        *reinterpret_cast<u32*>(smem + B_OFF + i * 4) = 0;
    if (tid < RPB)
        *reinterpret_cast<float*>(smem + XBUF_OFF + tid * 4) = x[(r0 + tid) * SEQ];

    // epilogue constants for rows ja, ja+8
    const int ja = 16 * w + g;
    const float wi0 = Wi[ja],     b0 = b[ja];
    const float wi1 = Wi[ja + 8], b1 = b[ja + 8];
    const bool is_tanh = ((w >> 3) == 2);    // warps 16..23 hold the g gate

    // update role: one (p_u, r_u) item per thread
    const int r_u = tid >> 7;            // 0..7
    const int p_u = tid & 127;
    const int pi = p_u & 15, pj = pi & 7;
    const int F  = (pj >> 1) * 8 + (pi >> 3) * 4 + (pj & 1) * 2 + r_u * 32;
    const int off_b = (p_u >> 4) * 512 + (F >> 3) * 16 + (F & 7);   // hi; lo at +8
    float c_st = 0.f, h_st = 0.f;

    __syncthreads();

    // ============ sequential loop ============
    for (int s = 0; s < SEQ; s++) {
        float xn = 0.f;
        if (tid < RPB && s + 1 < SEQ) xn = x[(r0 + tid) * SEQ + s + 1];

        // ---- MMA: one accumulator, hi + lo passes (h_lo stored unscaled) ----
        float d[4] = {0.f, 0.f, 0.f, 0.f};
#pragma unroll
        for (int kt = 0; kt < 8; kt++) {
            uint4 bv = *reinterpret_cast<const uint4*>(smem + B_OFF + kt * 512 + lane * 16);
            mma_f16(d, areg[kt], bv.x, bv.y);   // A * h_hi
            mma_f16(d, areg[kt], bv.z, bv.w);   // A * h_lo (exact residual)
        }

        // ---- epilogue: + x*Wi + b, activation, store gates ----
        const float* xs = reinterpret_cast<const float*>(smem + XBUF_OFF + (s & 1) * 32);
        float x0 = xs[2 * q], x1 = xs[2 * q + 1];
        float v[4];
        v[0] = d[0] + x0 * wi0 + b0;
        v[1] = d[1] + x1 * wi0 + b0;
        v[2] = d[2] + x0 * wi1 + b1;
        v[3] = d[3] + x1 * wi1 + b1;
        act4(v, is_tanh);

        float* gs = reinterpret_cast<float*>(smem + GS_OFF);
        gs[(2 * q)     * GS_STRIDE + ja]     = v[0];
        gs[(2 * q + 1) * GS_STRIDE + ja]     = v[1];
        gs[(2 * q)     * GS_STRIDE + ja + 8] = v[2];
        gs[(2 * q + 1) * GS_STRIDE + ja + 8] = v[3];

        __syncthreads();   // gates visible; B-frag reads complete

        // ---- update: 1 item/thread; write fused B frag (fp16 hi | lo) ----
        {
            const float* gsr = reinterpret_cast<const float*>(smem + GS_OFF);
            float iv = gsr[r_u * GS_STRIDE + p_u];
            float fv = gsr[r_u * GS_STRIDE + p_u + 128];
            float gg = gsr[r_u * GS_STRIDE + p_u + 256];
            float ov = gsr[r_u * GS_STRIDE + p_u + 384];
            c_st = fv * c_st + iv * gg;
            float h = ov * fast_tanh1(c_st);
            h_st = h;
            __half hh = __float2half_rn(h);
            float  hf = __half2float(hh);
            __half hl = __float2half_rn(h - hf);      // unscaled residual
            *reinterpret_cast<unsigned short*>(smem + B_OFF + off_b) =
                *reinterpret_cast<unsigned short*>(&hh);
            *reinterpret_cast<unsigned short*>(smem + B_OFF + off_b + 8) =
                *reinterpret_cast<unsigned short*>(&hl);
            if (tid < RPB && s + 1 < SEQ)
                *reinterpret_cast<float*>(smem + XBUF_OFF + ((s + 1) & 1) * 32 + tid * 4) = xn;
        }

        __syncthreads();   // new B tiles + x published
    }

    // ============ output: out[r] = h . Wd + bd ============
    {
        float* red = reinterpret_cast<float*>(smem + RED_OFF);
        red[p_u * 8 + r_u] = h_st * Wd[p_u];
    }
    __syncthreads();
    if (tid < RPB) {
        const float* red = reinterpret_cast<const float*>(smem + RED_OFF);
        float sum = 0.f;
        for (int pp = 0; pp < HID; pp++) sum += red[pp * 8 + tid];
        out[r0 + tid] = sum + bd[0];
    }
}

extern "C" void kernel_launch(void* const* d_in, const int* in_sizes, int n_in,
                              void* d_out, int out_size)
{
    (void)in_sizes; (void)n_in; (void)out_size;
    const float* x  = (const float*)d_in[0];
    const float* Wi = (const float*)d_in[1];
    const float* Wh = (const float*)d_in[2];
    const float* b  = (const float*)d_in[3];
    const float* Wd = (const float*)d_in[4];
    const float* bd = (const float*)d_in[5];
    float* out = (float*)d_out;

    cudaFuncSetAttribute(lstm_w32_kernel,
                         cudaFuncAttributeMaxDynamicSharedMemorySize, SMEM_TOTAL);
    lstm_w32_kernel<<<NCTA, THREADS, SMEM_TOTAL>>>(x, Wi, Wh, b, Wd, bd, out);
}

// round 7
// speedup vs baseline: 1.4459x; 1.4459x over previous
#include <cuda_runtime.h>
#include <cuda_fp16.h>

#define THREADS 512
#define RPB     8
#define NCTA    128
#define SEQ     1024
#define GATES   512
#define HID     128

// ---- smem byte offsets ----
#define B_OFF     0         // B frags, double buffered: 2 * 8kt * 256B = 4096
#define XBUF_OFF  4096      // x double buffer 2*8 f32 = 64
#define RED_OFF   4160      // output reduction 128*8 f32 = 4096
#define SMEM_TOTAL 8256

#define LOG2E 1.4426950408889634f

typedef unsigned int u32;

static __device__ __forceinline__ void mma_f16(float* d, const uint4& a, u32 b0, u32 b1) {
    asm volatile("mma.sync.aligned.m16n8k16.row.col.f32.f16.f16.f32 "
        "{%0,%1,%2,%3}, {%4,%5,%6,%7}, {%8,%9}, {%0,%1,%2,%3};"
        : "+f"(d[0]), "+f"(d[1]), "+f"(d[2]), "+f"(d[3])
        : "r"(a.x), "r"(a.y), "r"(a.z), "r"(a.w), "r"(b0), "r"(b1));
}
static __device__ __forceinline__ float ex2f(float x) {
    float r; asm("ex2.approx.f32 %0, %1;" : "=f"(r) : "f"(x)); return r;
}
static __device__ __forceinline__ float rcpf(float x) {
    float r; asm("rcp.approx.f32 %0, %1;" : "=f"(r) : "f"(x)); return r;
}
static __device__ __forceinline__ u32 pack_h2(float a, float b) {
    __half2 h = __halves2half2(__float2half_rn(a), __float2half_rn(b));
    return *reinterpret_cast<u32*>(&h);
}

// v[0],v[1]: sigmoid. v[2],v[3]: tanh if t23 else sigmoid. ONE rcp total.
static __device__ __forceinline__ void act4m(float* v, bool t23) {
    float k23 = t23 ? (2.f * LOG2E) : (-LOG2E);
    float L23 = t23 ? 8.f : 14.f;
    float e0 = ex2f(fminf(fmaxf(v[0], -14.f), 14.f) * (-LOG2E));
    float e1 = ex2f(fminf(fmaxf(v[1], -14.f), 14.f) * (-LOG2E));
    float e2 = ex2f(fminf(fmaxf(v[2], -L23), L23) * k23);
    float e3 = ex2f(fminf(fmaxf(v[3], -L23), L23) * k23);
    float d0 = e0 + 1.f, d1 = e1 + 1.f, d2 = e2 + 1.f, d3 = e3 + 1.f;
    float n2 = t23 ? (e2 - 1.f) : 1.f;
    float n3 = t23 ? (e3 - 1.f) : 1.f;
    float p01 = d0 * d1, p23 = d2 * d3;
    float r = rcpf(p01 * p23);
    v[0] = r * d1 * p23;
    v[1] = r * d0 * p23;
    v[2] = n2 * (r * p01 * d3);
    v[3] = n3 * (r * p01 * d2);
}
// tanh of 4 values, ONE rcp (clamp +-9: e^18^4 ~ 1.9e31, no overflow)
static __device__ __forceinline__ void tanh4(const float* c, float* t) {
    float e0 = ex2f(fminf(fmaxf(c[0], -9.f), 9.f) * (2.f * LOG2E));
    float e1 = ex2f(fminf(fmaxf(c[1], -9.f), 9.f) * (2.f * LOG2E));
    float e2 = ex2f(fminf(fmaxf(c[2], -9.f), 9.f) * (2.f * LOG2E));
    float e3 = ex2f(fminf(fmaxf(c[3], -9.f), 9.f) * (2.f * LOG2E));
    float d0 = e0 + 1.f, d1 = e1 + 1.f, d2 = e2 + 1.f, d3 = e3 + 1.f;
    float p01 = d0 * d1, p23 = d2 * d3;
    float r = rcpf(p01 * p23);
    t[0] = (e0 - 1.f) * (r * d1 * p23);
    t[1] = (e1 - 1.f) * (r * d0 * p23);
    t[2] = (e2 - 1.f) * (r * p01 * d3);
    t[3] = (e3 - 1.f) * (r * p01 * d2);
}

__global__ void __launch_bounds__(THREADS, 1)
lstm_1bar_kernel(const float* __restrict__ x,  const float* __restrict__ Wi,
                 const float* __restrict__ Wh, const float* __restrict__ b,
                 const float* __restrict__ Wd, const float* __restrict__ bd,
                 float* __restrict__ out)
{
    extern __shared__ char smem[];
    const int tid  = threadIdx.x;
    const int w    = tid >> 5;           // warp 0..15
    const int lane = tid & 31;
    const int g    = lane >> 2;          // 0..7
    const int q    = lane & 3;
    const bool upper = (g >= 4);         // lanes 16..31 hold f,o and run the update
    const int r0   = blockIdx.x * RPB;

    // ---- gate-fused m-tiles: m-row m -> global row j = (m>>2)*128 + (4*hg + (m&3))
    // thread (g,q) holds rows m=g (gate g>>2 in {0,1}) and m=g+8 (gate (g>>2)+2)
    int p[2], j0[2];
#pragma unroll
    for (int mt = 0; mt < 2; mt++) {
        p[mt]  = 4 * (2 * w + mt) + (g & 3);        // hid owned in this m-tile
        j0[mt] = ((g >> 2) << 7) + p[mt];           // gate 0/1 row; gate 2/3 = +256
    }

    // ---- A = Wh^T fp16 fragments -> registers (permuted rows) ----
    uint4 areg[2][8];
#pragma unroll
    for (int mt = 0; mt < 2; mt++) {
        int jA = j0[mt], jB = j0[mt] + 256;
#pragma unroll
        for (int kt = 0; kt < 8; kt++) {
            int c0 = kt * 16 + 2 * q, c2 = c0 + 8;
            areg[mt][kt].x = pack_h2(Wh[c0 * GATES + jA], Wh[(c0 + 1) * GATES + jA]);
            areg[mt][kt].y = pack_h2(Wh[c0 * GATES + jB], Wh[(c0 + 1) * GATES + jB]);
            areg[mt][kt].z = pack_h2(Wh[c2 * GATES + jA], Wh[(c2 + 1) * GATES + jA]);
            areg[mt][kt].w = pack_h2(Wh[c2 * GATES + jB], Wh[(c2 + 1) * GATES + jB]);
        }
    }
    float wiA[2], bA[2], wiB[2], bB[2];
#pragma unroll
    for (int mt = 0; mt < 2; mt++) {
        wiA[mt] = Wi[j0[mt]];       bA[mt] = b[j0[mt]];
        wiB[mt] = Wi[j0[mt] + 256]; bB[mt] = b[j0[mt] + 256];
    }

    // B-frag writer offsets (uint2/lane layout): value (k=p, n=r) ->
    // kt*256 + (r*4 + ((p&7)>>1))*8 + ((p&15)>=8 ? 4 : 0) + (p&1)*2
    int offc[2];
#pragma unroll
    for (int mt = 0; mt < 2; mt++) {
        int pp = p[mt];
        offc[mt] = (pp >> 4) * 256 + ((pp & 7) >> 1) * 8
                 + (((pp & 15) >= 8) ? 4 : 0) + (pp & 1) * 2;
    }

    // zero both B buffers (h0 = 0)
    for (int i = tid; i < 4096 / 4; i += THREADS)
        *reinterpret_cast<u32*>(smem + B_OFF + i * 4) = 0;
    float* xbuf = reinterpret_cast<float*>(smem + XBUF_OFF);
    if (tid < RPB) xbuf[tid] = x[(r0 + tid) * SEQ];

    float c_st[4] = {0.f, 0.f, 0.f, 0.f};   // (mt0,r=2q),(mt0,2q+1),(mt1,2q),(mt1,2q+1)
    float hk[4]   = {0.f, 0.f, 0.f, 0.f};

    __syncthreads();

    // ============ sequential loop: ONE barrier per step ============
    for (int s = 0; s < SEQ; s++) {
        float xn = 0.f;
        if (tid < RPB && s + 1 < SEQ) xn = x[(r0 + tid) * SEQ + s + 1];

        const char* Bc = smem + B_OFF + (s & 1) * 2048;
        float d0[4] = {0.f, 0.f, 0.f, 0.f};
        float d1[4] = {0.f, 0.f, 0.f, 0.f};
#pragma unroll
        for (int kt = 0; kt < 8; kt++) {
            uint2 bv = *reinterpret_cast<const uint2*>(Bc + kt * 256 + lane * 8);
            mma_f16(d0, areg[0][kt], bv.x, bv.y);
            mma_f16(d1, areg[1][kt], bv.x, bv.y);
        }

        // ---- + x*Wi + b, activations ----
        const float* xs = xbuf + (s & 1) * 8;
        float x0 = xs[2 * q], x1 = xs[2 * q + 1];
        float v0[4], v1[4];
        v0[0] = d0[0] + x0 * wiA[0] + bA[0];   // gate 0/1 (always sigmoid)
        v0[1] = d0[1] + x1 * wiA[0] + bA[0];
        v0[2] = d0[2] + x0 * wiB[0] + bB[0];   // gate 2 (tanh) on lower, 3 (sig) on upper
        v0[3] = d0[3] + x1 * wiB[0] + bB[0];
        v1[0] = d1[0] + x0 * wiA[1] + bA[1];
        v1[1] = d1[1] + x1 * wiA[1] + bA[1];
        v1[2] = d1[2] + x0 * wiB[1] + bB[1];
        v1[3] = d1[3] + x1 * wiB[1] + bB[1];
        const bool t23 = !upper;
        act4m(v0, t23);
        act4m(v1, t23);

        // ---- in-warp update: lower lanes own i*g, shfl to upper (f,o,c,h) ----
        float igA = v0[0] * v0[2], igB = v0[1] * v0[3];
        float igC = v1[0] * v1[2], igD = v1[1] * v1[3];
        igA = __shfl_xor_sync(0xffffffffu, igA, 16);
        igB = __shfl_xor_sync(0xffffffffu, igB, 16);
        igC = __shfl_xor_sync(0xffffffffu, igC, 16);
        igD = __shfl_xor_sync(0xffffffffu, igD, 16);

        char* Bn = smem + B_OFF + ((s + 1) & 1) * 2048;
        if (upper) {
            c_st[0] = v0[0] * c_st[0] + igA;
            c_st[1] = v0[1] * c_st[1] + igB;
            c_st[2] = v1[0] * c_st[2] + igC;
            c_st[3] = v1[1] * c_st[3] + igD;
            float t[4];
            tanh4(c_st, t);
            hk[0] = v0[2] * t[0];
            hk[1] = v0[3] * t[1];
            hk[2] = v1[2] * t[2];
            hk[3] = v1[3] * t[3];
            __half h0 = __float2half_rn(hk[0]), h1 = __float2half_rn(hk[1]);
            __half h2 = __float2half_rn(hk[2]), h3 = __float2half_rn(hk[3]);
            *reinterpret_cast<unsigned short*>(Bn + offc[0] + (2 * q) * 32)     = *reinterpret_cast<unsigned short*>(&h0);
            *reinterpret_cast<unsigned short*>(Bn + offc[0] + (2 * q + 1) * 32) = *reinterpret_cast<unsigned short*>(&h1);
            *reinterpret_cast<unsigned short*>(Bn + offc[1] + (2 * q) * 32)     = *reinterpret_cast<unsigned short*>(&h2);
            *reinterpret_cast<unsigned short*>(Bn + offc[1] + (2 * q + 1) * 32) = *reinterpret_cast<unsigned short*>(&h3);
        }
        if (tid < RPB && s + 1 < SEQ) xbuf[((s + 1) & 1) * 8 + tid] = xn;

        __syncthreads();   // B[nxt] + xbuf[nxt] published; B[cur] reads all done
    }

    // ============ output: out[r] = h . Wd + bd ============
    float* red = reinterpret_cast<float*>(smem + RED_OFF);
    if (upper) {
        float wd0 = Wd[p[0]], wd1 = Wd[p[1]];
        red[p[0] * 8 + 2 * q]     = hk[0] * wd0;
        red[p[0] * 8 + 2 * q + 1] = hk[1] * wd0;
        red[p[1] * 8 + 2 * q]     = hk[2] * wd1;
        red[p[1] * 8 + 2 * q + 1] = hk[3] * wd1;
    }
    __syncthreads();
    if (tid < RPB) {
        float sum = 0.f;
        for (int pp = 0; pp < HID; pp++) sum += red[pp * 8 + tid];
        out[r0 + tid] = sum + bd[0];
    }
}

extern "C" void kernel_launch(void* const* d_in, const int* in_sizes, int n_in,
                              void* d_out, int out_size)
{
    (void)in_sizes; (void)n_in; (void)out_size;
    const float* x  = (const float*)d_in[0];
    const float* Wi = (const float*)d_in[1];
    const float* Wh = (const float*)d_in[2];
    const float* b  = (const float*)d_in[3];
    const float* Wd = (const float*)d_in[4];
    const float* bd = (const float*)d_in[5];
    float* out = (float*)d_out;

    cudaFuncSetAttribute(lstm_1bar_kernel,
                         cudaFuncAttributeMaxDynamicSharedMemorySize, SMEM_TOTAL);
    lstm_1bar_kernel<<<NCTA, THREADS, SMEM_TOTAL>>>(x, Wi, Wh, b, Wd, bd, out);
}

// round 8
// speedup vs baseline: 1.9266x; 1.3324x over previous
#include <cuda_runtime.h>
#include <cuda_fp16.h>

#define THREADS 512
#define RPB     8
#define NCTA    128
#define SEQ     1024
#define GATES   512
#define HID     128

// ---- smem byte offsets ----
#define B_OFF     0         // B frags, double buffered: 2 * 8kt * 256B = 4096
#define XBUF_OFF  4096      // x double buffer 2*8 f32 = 64
#define RED_OFF   4160      // output reduction 128*8 f32 = 4096
#define SMEM_TOTAL 8256

typedef unsigned int u32;

static __device__ __forceinline__ void mma_f16(float* d, const uint4& a, u32 b0, u32 b1) {
    asm volatile("mma.sync.aligned.m16n8k16.row.col.f32.f16.f16.f32 "
        "{%0,%1,%2,%3}, {%4,%5,%6,%7}, {%8,%9}, {%0,%1,%2,%3};"
        : "+f"(d[0]), "+f"(d[1]), "+f"(d[2]), "+f"(d[3])
        : "r"(a.x), "r"(a.y), "r"(a.z), "r"(a.w), "r"(b0), "r"(b1));
}
static __device__ __forceinline__ float tanhap(float x) {
    float r; asm("tanh.approx.f32 %0, %1;" : "=f"(r) : "f"(x)); return r;
}
static __device__ __forceinline__ float sigap(float x) {
    return fmaf(0.5f, tanhap(0.5f * x), 0.5f);
}
static __device__ __forceinline__ u32 pack_h2(float a, float b) {
    __half2 h = __halves2half2(__float2half_rn(a), __float2half_rn(b));
    return *reinterpret_cast<u32*>(&h);
}

__global__ void __launch_bounds__(THREADS, 1)
lstm_mufu_kernel(const float* __restrict__ x,  const float* __restrict__ Wi,
                 const float* __restrict__ Wh, const float* __restrict__ b,
                 const float* __restrict__ Wd, const float* __restrict__ bd,
                 float* __restrict__ out)
{
    extern __shared__ char smem[];
    const int tid  = threadIdx.x;
    const int w    = tid >> 5;           // warp 0..15
    const int lane = tid & 31;
    const int g    = lane >> 2;          // 0..7
    const int q    = lane & 3;
    const bool upper = (g >= 4);         // lanes 16..31 hold f,o and run the update
    const int r0   = blockIdx.x * RPB;

    // gate-fused m-tiles: thread holds rows j0 (gate 0/1) and j0+256 (gate 2/3)
    int p[2], j0[2];
#pragma unroll
    for (int mt = 0; mt < 2; mt++) {
        p[mt]  = 4 * (2 * w + mt) + (g & 3);
        j0[mt] = ((g >> 2) << 7) + p[mt];
    }

    // ---- A = Wh^T fp16 fragments -> registers (permuted rows) ----
    uint4 areg[2][8];
#pragma unroll
    for (int mt = 0; mt < 2; mt++) {
        int jA = j0[mt], jB = j0[mt] + 256;
#pragma unroll
        for (int kt = 0; kt < 8; kt++) {
            int c0 = kt * 16 + 2 * q, c2 = c0 + 8;
            areg[mt][kt].x = pack_h2(Wh[c0 * GATES + jA], Wh[(c0 + 1) * GATES + jA]);
            areg[mt][kt].y = pack_h2(Wh[c0 * GATES + jB], Wh[(c0 + 1) * GATES + jB]);
            areg[mt][kt].z = pack_h2(Wh[c2 * GATES + jA], Wh[(c2 + 1) * GATES + jA]);
            areg[mt][kt].w = pack_h2(Wh[c2 * GATES + jB], Wh[(c2 + 1) * GATES + jB]);
        }
    }
    float wiA[2], bA[2], wiB[2], bB[2];
#pragma unroll
    for (int mt = 0; mt < 2; mt++) {
        wiA[mt] = Wi[j0[mt]];       bA[mt] = b[j0[mt]];
        wiB[mt] = Wi[j0[mt] + 256]; bB[mt] = b[j0[mt] + 256];
    }

    // B-frag writer offsets
    int offc[2];
#pragma unroll
    for (int mt = 0; mt < 2; mt++) {
        int pp = p[mt];
        offc[mt] = (pp >> 4) * 256 + ((pp & 7) >> 1) * 8
                 + (((pp & 15) >= 8) ? 4 : 0) + (pp & 1) * 2;
    }

    // zero both B buffers (h0 = 0)
    for (int i = tid; i < 4096 / 4; i += THREADS)
        *reinterpret_cast<u32*>(smem + B_OFF + i * 4) = 0;
    float* xbuf = reinterpret_cast<float*>(smem + XBUF_OFF);
    if (tid < RPB) xbuf[tid] = x[(r0 + tid) * SEQ];

    float c_st[4] = {0.f, 0.f, 0.f, 0.f};
    float hk[4]   = {0.f, 0.f, 0.f, 0.f};

    __syncthreads();

    // ============ sequential loop: ONE barrier per step ============
#pragma unroll 2
    for (int s = 0; s < SEQ; s++) {
        float xn = 0.f;
        if (tid < RPB && s + 1 < SEQ) xn = x[(r0 + tid) * SEQ + s + 1];

        const char* Bc = smem + B_OFF + (s & 1) * 2048;
        // bias folded into accumulator init
        float d0[4] = {bA[0], bA[0], bB[0], bB[0]};
        float d1[4] = {bA[1], bA[1], bB[1], bB[1]};
#pragma unroll
        for (int kt = 0; kt < 8; kt++) {
            uint2 bv = *reinterpret_cast<const uint2*>(Bc + kt * 256 + lane * 8);
            mma_f16(d0, areg[0][kt], bv.x, bv.y);
            mma_f16(d1, areg[1][kt], bv.x, bv.y);
        }

        // ---- + x*Wi, activations (MUFU.TANH) ----
        const float* xs = xbuf + (s & 1) * 8;
        float x0 = xs[2 * q], x1 = xs[2 * q + 1];
        float v0[4], v1[4];
        v0[0] = fmaf(x0, wiA[0], d0[0]);
        v0[1] = fmaf(x1, wiA[0], d0[1]);
        v0[2] = fmaf(x0, wiB[0], d0[2]);
        v0[3] = fmaf(x1, wiB[0], d0[3]);
        v1[0] = fmaf(x0, wiA[1], d1[0]);
        v1[1] = fmaf(x1, wiA[1], d1[1]);
        v1[2] = fmaf(x0, wiB[1], d1[2]);
        v1[3] = fmaf(x1, wiB[1], d1[3]);
        // rows A: gates 0/1 (i or f) -> sigmoid always.
        // rows B: gate 2 (g, tanh) on lower lanes; gate 3 (o, sigmoid) on upper.
        v0[0] = sigap(v0[0]);  v0[1] = sigap(v0[1]);
        v1[0] = sigap(v1[0]);  v1[1] = sigap(v1[1]);
        if (upper) {
            v0[2] = sigap(v0[2]);  v0[3] = sigap(v0[3]);
            v1[2] = sigap(v1[2]);  v1[3] = sigap(v1[3]);
        } else {
            v0[2] = tanhap(v0[2]); v0[3] = tanhap(v0[3]);
            v1[2] = tanhap(v1[2]); v1[3] = tanhap(v1[3]);
        }

        // ---- in-warp update: lower lanes hold i*g, shfl to upper ----
        float igA = v0[0] * v0[2], igB = v0[1] * v0[3];
        float igC = v1[0] * v1[2], igD = v1[1] * v1[3];
        igA = __shfl_xor_sync(0xffffffffu, igA, 16);
        igB = __shfl_xor_sync(0xffffffffu, igB, 16);
        igC = __shfl_xor_sync(0xffffffffu, igC, 16);
        igD = __shfl_xor_sync(0xffffffffu, igD, 16);

        char* Bn = smem + B_OFF + ((s + 1) & 1) * 2048;
        if (upper) {
            c_st[0] = fmaf(v0[0], c_st[0], igA);
            c_st[1] = fmaf(v0[1], c_st[1], igB);
            c_st[2] = fmaf(v1[0], c_st[2], igC);
            c_st[3] = fmaf(v1[1], c_st[3], igD);
            hk[0] = v0[2] * tanhap(c_st[0]);
            hk[1] = v0[3] * tanhap(c_st[1]);
            hk[2] = v1[2] * tanhap(c_st[2]);
            hk[3] = v1[3] * tanhap(c_st[3]);
            __half h0 = __float2half_rn(hk[0]), h1 = __float2half_rn(hk[1]);
            __half h2 = __float2half_rn(hk[2]), h3 = __float2half_rn(hk[3]);
            *reinterpret_cast<unsigned short*>(Bn + offc[0] + (2 * q) * 32)     = *reinterpret_cast<unsigned short*>(&h0);
            *reinterpret_cast<unsigned short*>(Bn + offc[0] + (2 * q + 1) * 32) = *reinterpret_cast<unsigned short*>(&h1);
            *reinterpret_cast<unsigned short*>(Bn + offc[1] + (2 * q) * 32)     = *reinterpret_cast<unsigned short*>(&h2);
            *reinterpret_cast<unsigned short*>(Bn + offc[1] + (2 * q + 1) * 32) = *reinterpret_cast<unsigned short*>(&h3);
        }
        if (tid < RPB && s + 1 < SEQ) xbuf[((s + 1) & 1) * 8 + tid] = xn;

        __syncthreads();   // B[nxt] + xbuf[nxt] published; B[cur] reads done
    }

    // ============ output: out[r] = h . Wd + bd ============
    float* red = reinterpret_cast<float*>(smem + RED_OFF);
    if (upper) {
        float wd0 = Wd[p[0]], wd1 = Wd[p[1]];
        red[p[0] * 8 + 2 * q]     = hk[0] * wd0;
        red[p[0] * 8 + 2 * q + 1] = hk[1] * wd0;
        red[p[1] * 8 + 2 * q]     = hk[2] * wd1;
        red[p[1] * 8 + 2 * q + 1] = hk[3] * wd1;
    }
    __syncthreads();
    if (tid < RPB) {
        float sum = 0.f;
        for (int pp = 0; pp < HID; pp++) sum += red[pp * 8 + tid];
        out[r0 + tid] = sum + bd[0];
    }
}

extern "C" void kernel_launch(void* const* d_in, const int* in_sizes, int n_in,
                              void* d_out, int out_size)
{
    (void)in_sizes; (void)n_in; (void)out_size;
    const float* x  = (const float*)d_in[0];
    const float* Wi = (const float*)d_in[1];
    const float* Wh = (const float*)d_in[2];
    const float* b  = (const float*)d_in[3];
    const float* Wd = (const float*)d_in[4];
    const float* bd = (const float*)d_in[5];
    float* out = (float*)d_out;

    cudaFuncSetAttribute(lstm_mufu_kernel,
                         cudaFuncAttributeMaxDynamicSharedMemorySize, SMEM_TOTAL);
    lstm_mufu_kernel<<<NCTA, THREADS, SMEM_TOTAL>>>(x, Wi, Wh, b, Wd, bd, out);
}

// round 9
// speedup vs baseline: 2.4257x; 1.2591x over previous
#include <cuda_runtime.h>
#include <cuda_fp16.h>

#define THREADS 512
#define RPB     8
#define NCTA    128
#define SEQ     1024
#define GATES   512
#define HID     128

// ---- smem ----
#define B_OFF     0         // B frags, double buffered: 2 * 8kt * 256B = 4096
#define RED_OFF   4096      // output reduction 128*8 f32 = 4096
#define SMEM_TOTAL 8192

typedef unsigned int u32;

static __device__ __forceinline__ void mma_f16(float* d, const uint4& a, u32 b0, u32 b1) {
    asm volatile("mma.sync.aligned.m16n8k16.row.col.f32.f16.f16.f32 "
        "{%0,%1,%2,%3}, {%4,%5,%6,%7}, {%8,%9}, {%0,%1,%2,%3};"
        : "+f"(d[0]), "+f"(d[1]), "+f"(d[2]), "+f"(d[3])
        : "r"(a.x), "r"(a.y), "r"(a.z), "r"(a.w), "r"(b0), "r"(b1));
}
static __device__ __forceinline__ float tanhap(float x) {
    float r; asm("tanh.approx.f32 %0, %1;" : "=f"(r) : "f"(x)); return r;
}
static __device__ __forceinline__ float sigap(float x) {
    return fmaf(0.5f, tanhap(0.5f * x), 0.5f);
}
static __device__ __forceinline__ u32 pack_h2(float a, float b) {
    __half2 h = __halves2half2(__float2half_rn(a), __float2half_rn(b));
    return *reinterpret_cast<u32*>(&h);
}

__global__ void __launch_bounds__(THREADS, 1)
lstm_noshfl_kernel(const float* __restrict__ x,  const float* __restrict__ Wi,
                   const float* __restrict__ Wh, const float* __restrict__ b,
                   const float* __restrict__ Wd, const float* __restrict__ bd,
                   float* __restrict__ out)
{
    extern __shared__ char smem[];
    const int tid  = threadIdx.x;
    const int w    = tid >> 5;           // warp 0..15: hid set 8w..8w+7
    const int lane = tid & 31;
    const int g    = lane >> 2;          // 0..7 -> hid p = 8w+g
    const int q    = lane & 3;           // rows 2q, 2q+1
    const int r0   = blockIdx.x * RPB;
    const int p    = 8 * w + g;          // my hid

    // gate-paired m-tiles (same hid set in both):
    //   mt0 rows 0-7 = i-gate (j=p),    rows 8-15 = g-gate (j=256+p)
    //   mt1 rows 0-7 = f-gate (j=128+p),rows 8-15 = o-gate (j=384+p)
    const int jrow[2][2] = { { p, 256 + p }, { 128 + p, 384 + p } };

    // ---- A = Wh^T fp16 fragments -> registers ----
    uint4 areg[2][8];
#pragma unroll
    for (int mt = 0; mt < 2; mt++) {
        int jA = jrow[mt][0], jB = jrow[mt][1];
#pragma unroll
        for (int kt = 0; kt < 8; kt++) {
            int c0 = kt * 16 + 2 * q, c2 = c0 + 8;
            areg[mt][kt].x = pack_h2(Wh[c0 * GATES + jA], Wh[(c0 + 1) * GATES + jA]);
            areg[mt][kt].y = pack_h2(Wh[c0 * GATES + jB], Wh[(c0 + 1) * GATES + jB]);
            areg[mt][kt].z = pack_h2(Wh[c2 * GATES + jA], Wh[(c2 + 1) * GATES + jA]);
            areg[mt][kt].w = pack_h2(Wh[c2 * GATES + jB], Wh[(c2 + 1) * GATES + jB]);
        }
    }
    const float wi_i = Wi[p],       bi = b[p];
    const float wi_g = Wi[256 + p], bg = b[256 + p];
    const float wi_f = Wi[128 + p], bf = b[128 + p];
    const float wi_o = Wi[384 + p], bo = b[384 + p];

    // B-frag writer offsets for (k=p, n=2q / 2q+1)
    const int offc = (p >> 4) * 256 + ((p & 7) >> 1) * 8
                   + (((p & 15) >= 8) ? 4 : 0) + (p & 1) * 2;
    const int off0 = offc + (2 * q) * 32;
    const int off1 = offc + (2 * q + 1) * 32;

    // zero both B buffers (h0 = 0)
    for (int i = tid; i < 4096 / 4; i += THREADS)
        *reinterpret_cast<u32*>(smem + B_OFF + i * 4) = 0;

    // x stream: rows 2q, 2q+1 via gmem broadcast loads (L1-hit after first)
    const float* xr0 = x + (r0 + 2 * q) * SEQ;
    const float* xr1 = x + (r0 + 2 * q + 1) * SEQ;
    float x0c = xr0[0], x1c = xr1[0];

    float c0 = 0.f, c1 = 0.f, h0f = 0.f, h1f = 0.f;

    __syncthreads();

    // ============ sequential loop: ONE barrier per step ============
#pragma unroll 2
    for (int s = 0; s < SEQ; s++) {
        int sn = (s + 1 < SEQ) ? s + 1 : s;
        float x0n = xr0[sn], x1n = xr1[sn];

        const char* Bc = smem + B_OFF + (s & 1) * 2048;
        // split accumulator chains (dep depth 8 -> 4); bias folded into init
        float dAa[4] = {bi, bi, bg, bg};
        float dAb[4] = {0.f, 0.f, 0.f, 0.f};
        float dBa[4] = {bf, bf, bo, bo};
        float dBb[4] = {0.f, 0.f, 0.f, 0.f};
#pragma unroll
        for (int kt = 0; kt < 4; kt++) {
            uint2 bv0 = *reinterpret_cast<const uint2*>(Bc + kt * 256 + lane * 8);
            uint2 bv1 = *reinterpret_cast<const uint2*>(Bc + (kt + 4) * 256 + lane * 8);
            mma_f16(dAa, areg[0][kt],     bv0.x, bv0.y);
            mma_f16(dBa, areg[1][kt],     bv0.x, bv0.y);
            mma_f16(dAb, areg[0][kt + 4], bv1.x, bv1.y);
            mma_f16(dBb, areg[1][kt + 4], bv1.x, bv1.y);
        }

        // ---- epilogue: all 4 gates live in this thread for rows 2q,2q+1 ----
        float vi0 = sigap(fmaf(x0c, wi_i, dAa[0] + dAb[0]));
        float vi1 = sigap(fmaf(x1c, wi_i, dAa[1] + dAb[1]));
        float vg0 = tanhap(fmaf(x0c, wi_g, dAa[2] + dAb[2]));
        float vg1 = tanhap(fmaf(x1c, wi_g, dAa[3] + dAb[3]));
        float vf0 = sigap(fmaf(x0c, wi_f, dBa[0] + dBb[0]));
        float vf1 = sigap(fmaf(x1c, wi_f, dBa[1] + dBb[1]));
        float vo0 = sigap(fmaf(x0c, wi_o, dBa[2] + dBb[2]));
        float vo1 = sigap(fmaf(x1c, wi_o, dBa[3] + dBb[3]));

        // ---- in-thread update (no shfl), 2 items ----
        c0 = fmaf(vf0, c0, vi0 * vg0);
        c1 = fmaf(vf1, c1, vi1 * vg1);
        h0f = vo0 * tanhap(c0);
        h1f = vo1 * tanhap(c1);

        char* Bn = smem + B_OFF + ((s + 1) & 1) * 2048;
        __half hh0 = __float2half_rn(h0f);
        __half hh1 = __float2half_rn(h1f);
        *reinterpret_cast<unsigned short*>(Bn + off0) = *reinterpret_cast<unsigned short*>(&hh0);
        *reinterpret_cast<unsigned short*>(Bn + off1) = *reinterpret_cast<unsigned short*>(&hh1);

        x0c = x0n; x1c = x1n;

        __syncthreads();   // B[nxt] published; B[cur] reads all complete
    }

    // ============ output: out[r] = h . Wd + bd ============
    float* red = reinterpret_cast<float*>(smem + RED_OFF);
    {
        float wd = Wd[p];
        red[p * 8 + 2 * q]     = h0f * wd;
        red[p * 8 + 2 * q + 1] = h1f * wd;
    }
    __syncthreads();
    if (tid < RPB) {
        float sum = 0.f;
        for (int pp = 0; pp < HID; pp++) sum += red[pp * 8 + tid];
        out[r0 + tid] = sum + bd[0];
    }
}

extern "C" void kernel_launch(void* const* d_in, const int* in_sizes, int n_in,
                              void* d_out, int out_size)
{
    (void)in_sizes; (void)n_in; (void)out_size;
    const float* x  = (const float*)d_in[0];
    const float* Wi = (const float*)d_in[1];
    const float* Wh = (const float*)d_in[2];
    const float* b  = (const float*)d_in[3];
    const float* Wd = (const float*)d_in[4];
    const float* bd = (const float*)d_in[5];
    float* out = (float*)d_out;

    cudaFuncSetAttribute(lstm_noshfl_kernel,
                         cudaFuncAttributeMaxDynamicSharedMemorySize, SMEM_TOTAL);
    lstm_noshfl_kernel<<<NCTA, THREADS, SMEM_TOTAL>>>(x, Wi, Wh, b, Wd, bd, out);
}

// round 10
// speedup vs baseline: 2.7390x; 1.1292x over previous
#include <cuda_runtime.h>
#include <cuda_fp16.h>

#define THREADS 512
#define RPB     8
#define NCTA    128
#define SEQ     1024
#define GATES   512
#define HID     128

// ---- smem ----
// B frags: [lane 0..31][kt 0..7 u64], lane stride 80B (conflict-free LDS.128)
#define B_STRIDE  80
#define B_BUF     2560      // 32 * 80
#define B_OFF     0         // double buffered: 2 * 2560 = 5120
#define RED_OFF   5120      // output reduction 128*8 f32 = 4096
#define SMEM_TOTAL 9216

typedef unsigned int u32;

// f16-accumulator HMMA (2x rate); D/C = 2 regs of packed half2 {col 2q, col 2q+1}
static __device__ __forceinline__ void mma_f16h(u32* d, const uint4& a, u32 b0, u32 b1) {
    asm volatile("mma.sync.aligned.m16n8k16.row.col.f16.f16.f16.f16 "
        "{%0,%1}, {%2,%3,%4,%5}, {%6,%7}, {%0,%1};"
        : "+r"(d[0]), "+r"(d[1])
        : "r"(a.x), "r"(a.y), "r"(a.z), "r"(a.w), "r"(b0), "r"(b1));
}
static __device__ __forceinline__ u32 tanh2(u32 v) {
    u32 r; asm("tanh.approx.f16x2 %0, %1;" : "=r"(r) : "r"(v)); return r;
}
static __device__ __forceinline__ u32 pack_h2(float a, float b) {   // a -> LOW half
    __half2 h = __halves2half2(__float2half_rn(a), __float2half_rn(b));
    return *reinterpret_cast<u32*>(&h);
}
static __device__ __forceinline__ __half2 asH2(u32 v) { return *reinterpret_cast<__half2*>(&v); }
static __device__ __forceinline__ u32 asU32(__half2 v) { return *reinterpret_cast<u32*>(&v); }

__global__ void __launch_bounds__(THREADS, 1)
lstm_h16_kernel(const float* __restrict__ x,  const float* __restrict__ Wi,
                const float* __restrict__ Wh, const float* __restrict__ b,
                const float* __restrict__ Wd, const float* __restrict__ bd,
                float* __restrict__ out)
{
    extern __shared__ char smem[];
    const int tid  = threadIdx.x;
    const int w    = tid >> 5;           // warp 0..15: hid set 8w..8w+7
    const int lane = tid & 31;
    const int g    = lane >> 2;          // hid p = 8w+g
    const int q    = lane & 3;           // batch rows 2q, 2q+1
    const int r0   = blockIdx.x * RPB;
    const int p    = 8 * w + g;

    // gate-paired m-tiles: mt0 = i(rows0-7)|g(rows8-15), mt1 = f|o.
    // Sigmoid gates (i,f,o) pre-scaled by 0.5 (weights, bias, Wi) so
    // sigmoid = 0.5*tanh(pre) + 0.5 with no extra scaling instructions.
    const int jI = p, jG = 256 + p, jF = 128 + p, jO = 384 + p;

    // ---- A = Wh^T fp16 fragments -> registers (i,f,o cols scaled 0.5) ----
    uint4 areg[2][8];
#pragma unroll
    for (int kt = 0; kt < 8; kt++) {
        int c0 = kt * 16 + 2 * q, c2 = c0 + 8;
        areg[0][kt].x = pack_h2(0.5f * Wh[c0 * GATES + jI], 0.5f * Wh[(c0 + 1) * GATES + jI]);
        areg[0][kt].y = pack_h2(Wh[c0 * GATES + jG],        Wh[(c0 + 1) * GATES + jG]);
        areg[0][kt].z = pack_h2(0.5f * Wh[c2 * GATES + jI], 0.5f * Wh[(c2 + 1) * GATES + jI]);
        areg[0][kt].w = pack_h2(Wh[c2 * GATES + jG],        Wh[(c2 + 1) * GATES + jG]);
        areg[1][kt].x = pack_h2(0.5f * Wh[c0 * GATES + jF], 0.5f * Wh[(c0 + 1) * GATES + jF]);
        areg[1][kt].y = pack_h2(0.5f * Wh[c0 * GATES + jO], 0.5f * Wh[(c0 + 1) * GATES + jO]);
        areg[1][kt].z = pack_h2(0.5f * Wh[c2 * GATES + jF], 0.5f * Wh[(c2 + 1) * GATES + jF]);
        areg[1][kt].w = pack_h2(0.5f * Wh[c2 * GATES + jO], 0.5f * Wh[(c2 + 1) * GATES + jO]);
    }
    const u32 biasI = pack_h2(0.5f * b[jI], 0.5f * b[jI]);
    const u32 biasG = pack_h2(b[jG], b[jG]);
    const u32 biasF = pack_h2(0.5f * b[jF], 0.5f * b[jF]);
    const u32 biasO = pack_h2(0.5f * b[jO], 0.5f * b[jO]);
    const __half2 wiI = asH2(pack_h2(0.5f * Wi[jI], 0.5f * Wi[jI]));
    const __half2 wiG = asH2(pack_h2(Wi[jG], Wi[jG]));
    const __half2 wiF = asH2(pack_h2(0.5f * Wi[jF], 0.5f * Wi[jF]));
    const __half2 wiO = asH2(pack_h2(0.5f * Wi[jO], 0.5f * Wi[jO]));
    const __half2 h05 = asH2(pack_h2(0.5f, 0.5f));

    // B-frag writer offsets: value (k=p, col=r) -> lane_t = r*4 + ((p&7)>>1),
    // byte = lane_t*80 + (p>>4)*8 + ((p&15)>=8 ? 4 : 0) + (p&1)*2
    const int lt0  = (2 * q) * 4 + ((p & 7) >> 1);
    const int off0 = lt0 * B_STRIDE + (p >> 4) * 8 + (((p & 15) >= 8) ? 4 : 0) + (p & 1) * 2;
    const int off1 = off0 + 4 * B_STRIDE;          // row 2q+1

    // zero both B buffers (h0 = 0)
    for (int i = tid; i < (2 * B_BUF) / 4; i += THREADS)
        *reinterpret_cast<u32*>(smem + B_OFF + i * 4) = 0;

    // x streams for my two batch rows (gmem broadcast, L1-resident)
    const float* xr0 = x + (r0 + 2 * q) * SEQ;
    const float* xr1 = x + (r0 + 2 * q + 1) * SEQ;
    float x0c = xr0[0], x1c = xr1[0];

    float c0 = 0.f, c1 = 0.f;
    __half2 h2v = asH2(0u);

    __syncthreads();

    // ============ sequential loop: ONE barrier per step ============
#pragma unroll 2
    for (int s = 0; s < SEQ; s++) {
        int sn = (s + 1 < SEQ) ? s + 1 : s;
        float x0n = xr0[sn], x1n = xr1[sn];

        const char* Bc = smem + B_OFF + (s & 1) * B_BUF + lane * B_STRIDE;
        // split accumulator chains; bias folded into first chain
        u32 dA[2]  = {biasI, biasG};
        u32 dAb[2] = {0u, 0u};
        u32 dB[2]  = {biasF, biasO};
        u32 dBb[2] = {0u, 0u};
#pragma unroll
        for (int i = 0; i < 4; i++) {
            uint4 bv = *reinterpret_cast<const uint4*>(Bc + i * 16);   // kt 2i, 2i+1
            mma_f16h(dA,  areg[0][2 * i],     bv.x, bv.y);
            mma_f16h(dB,  areg[1][2 * i],     bv.x, bv.y);
            mma_f16h(dAb, areg[0][2 * i + 1], bv.z, bv.w);
            mma_f16h(dBb, areg[1][2 * i + 1], bv.z, bv.w);
        }

        // ---- epilogue, all in half2 (batch-pair packed) ----
        __half2 x2 = asH2(pack_h2(x0c, x1c));
        __half2 vi = __hfma2(x2, wiI, __hadd2(asH2(dA[0]), asH2(dAb[0])));
        __half2 vg = __hfma2(x2, wiG, __hadd2(asH2(dA[1]), asH2(dAb[1])));
        __half2 vf = __hfma2(x2, wiF, __hadd2(asH2(dB[0]), asH2(dBb[0])));
        __half2 vo = __hfma2(x2, wiO, __hadd2(asH2(dB[1]), asH2(dBb[1])));

        __half2 i2 = __hfma2(asH2(tanh2(asU32(vi))), h05, h05);   // sigmoid(2*pre*0.5)
        __half2 g2 = asH2(tanh2(asU32(vg)));
        __half2 f2 = __hfma2(asH2(tanh2(asU32(vf))), h05, h05);
        __half2 o2 = __hfma2(asH2(tanh2(asU32(vo))), h05, h05);

        // ---- in-thread update: c in fp32 ----
        __half2 ig2 = __hmul2(i2, g2);
        c0 = fmaf(__low2float(f2),  c0, __low2float(ig2));
        c1 = fmaf(__high2float(f2), c1, __high2float(ig2));
        __half2 tc = asH2(tanh2(pack_h2(c0, c1)));
        h2v = __hmul2(o2, tc);

        char* Bn = smem + B_OFF + ((s + 1) & 1) * B_BUF;
        *reinterpret_cast<unsigned short*>(Bn + off0) = __half_as_ushort(__low2half(h2v));
        *reinterpret_cast<unsigned short*>(Bn + off1) = __half_as_ushort(__high2half(h2v));

        x0c = x0n; x1c = x1n;

        __syncthreads();   // B[nxt] published; B[cur] reads all complete
    }

    // ============ output: out[r] = h . Wd + bd ============
    float* red = reinterpret_cast<float*>(smem + RED_OFF);
    {
        float wd = Wd[p];
        red[p * 8 + 2 * q]     = __low2float(h2v) * wd;
        red[p * 8 + 2 * q + 1] = __high2float(h2v) * wd;
    }
    __syncthreads();
    if (tid < RPB) {
        float sum = 0.f;
        for (int pp = 0; pp < HID; pp++) sum += red[pp * 8 + tid];
        out[r0 + tid] = sum + bd[0];
    }
}

extern "C" void kernel_launch(void* const* d_in, const int* in_sizes, int n_in,
                              void* d_out, int out_size)
{
    (void)in_sizes; (void)n_in; (void)out_size;
    const float* x  = (const float*)d_in[0];
    const float* Wi = (const float*)d_in[1];
    const float* Wh = (const float*)d_in[2];
    const float* b  = (const float*)d_in[3];
    const float* Wd = (const float*)d_in[4];
    const float* bd = (const float*)d_in[5];
    float* out = (float*)d_out;

    cudaFuncSetAttribute(lstm_h16_kernel,
                         cudaFuncAttributeMaxDynamicSharedMemorySize, SMEM_TOTAL);
    lstm_h16_kernel<<<NCTA, THREADS, SMEM_TOTAL>>>(x, Wi, Wh, b, Wd, bd, out);
}